// round 1
// baseline (speedup 1.0000x reference)
#include <cuda_runtime.h>
#include <cuda_bf16.h>
#include <cstdint>

// Problem constants (match reference_code)
#define N_NODES 100000
#define N_EDGES 1200000
#define FEATS   64

// Scratch: sum accumulator [N, 64] and degree [N] (float so atomicAdd is uniform)
__device__ float g_sum[(size_t)N_NODES * FEATS];
__device__ float g_deg[N_NODES];

// ---------------------------------------------------------------------------
// Kernel 0: zero the scratch buffers
// ---------------------------------------------------------------------------
__global__ void zero_kernel() {
    const int total4 = (N_NODES * FEATS) / 4;   // 1.6M float4
    int idx = blockIdx.x * blockDim.x + threadIdx.x;
    int stride = gridDim.x * blockDim.x;
    float4 z = make_float4(0.f, 0.f, 0.f, 0.f);
    for (int i = idx; i < total4; i += stride)
        reinterpret_cast<float4*>(g_sum)[i] = z;
    for (int i = idx; i < N_NODES; i += stride)
        g_deg[i] = 0.f;
}

// ---------------------------------------------------------------------------
// Kernel 1: edge scatter.  One thread per (edge, 16-byte chunk): 16 threads/edge.
// Gather float4 from feature[src], RED.v4 into g_sum[dst].
// ---------------------------------------------------------------------------
__global__ void edge_kernel(const float* __restrict__ feat,
                            const int*  __restrict__ esrc,
                            const int*  __restrict__ edst) {
    long long idx = (long long)blockIdx.x * blockDim.x + threadIdx.x;
    int e = (int)(idx >> 4);
    int c = (int)(idx & 15);
    if (e >= N_EDGES) return;

    int s = __ldg(&esrc[e]);
    int d = __ldg(&edst[e]);

    const float4 v = *reinterpret_cast<const float4*>(&feat[(size_t)s * FEATS + c * 4]);
    float* p = &g_sum[(size_t)d * FEATS + c * 4];
    asm volatile("red.global.add.v4.f32 [%0], {%1, %2, %3, %4};"
                 :: "l"(p), "f"(v.x), "f"(v.y), "f"(v.z), "f"(v.w)
                 : "memory");

    if (c == 0) atomicAdd(&g_deg[d], 1.0f);
}

// ---------------------------------------------------------------------------
// Kernel 2: per-node mean + linear(64x64) + bias + relu
// Block: 256 threads = 4 nodes x 64 output-cols.
// W kept transposed in shared (Ws[d][o], padded) -> conflict-free LDS.
// ---------------------------------------------------------------------------
#define NODES_PER_BLOCK 4
__global__ __launch_bounds__(256, 8)
void node_kernel(const float* __restrict__ W,
                 const float* __restrict__ b,
                 float* __restrict__ out) {
    __shared__ float Ws[FEATS][FEATS + 1];            // Ws[d][o] = W[o][d]
    __shared__ float hs[NODES_PER_BLOCK][FEATS];

    int tid = threadIdx.x;
    // cooperative transpose-load of W (4096 elems / 256 threads = 16 each)
    #pragma unroll
    for (int i = tid; i < FEATS * FEATS; i += 256) {
        int o = i >> 6, d = i & 63;
        Ws[d][o] = W[i];
    }

    int nl = tid >> 6;        // node slot within block (0..3)
    int o  = tid & 63;        // output column (0..63)
    int node = blockIdx.x * NODES_PER_BLOCK + nl;

    if (node < N_NODES) {
        float dg = g_deg[node];
        float rdeg = 1.0f / fmaxf(dg, 1.0f);
        hs[nl][o] = g_sum[(size_t)node * FEATS + o] * rdeg;
    }
    __syncthreads();

    if (node >= N_NODES) return;

    float acc = __ldg(&b[o]);
    #pragma unroll
    for (int d = 0; d < FEATS; d++)
        acc = fmaf(Ws[d][o], hs[nl][d], acc);

    out[(size_t)node * FEATS + o] = fmaxf(acc, 0.0f);
}

// ---------------------------------------------------------------------------
extern "C" void kernel_launch(void* const* d_in, const int* in_sizes, int n_in,
                              void* d_out, int out_size) {
    const float* feat = (const float*)d_in[0];
    const int*   esrc = (const int*)  d_in[1];
    const int*   edst = (const int*)  d_in[2];
    const float* W    = (const float*)d_in[3];
    const float* b    = (const float*)d_in[4];
    float* out = (float*)d_out;

    zero_kernel<<<512, 256>>>();

    const long long edge_threads = (long long)N_EDGES * 16;
    int edge_blocks = (int)((edge_threads + 255) / 256);
    edge_kernel<<<edge_blocks, 256>>>(feat, esrc, edst);

    int node_blocks = (N_NODES + NODES_PER_BLOCK - 1) / NODES_PER_BLOCK;
    node_kernel<<<node_blocks, 256>>>(W, b, out);
}

// round 3
// speedup vs baseline: 1.0779x; 1.0779x over previous
#include <cuda_runtime.h>
#include <cuda_bf16.h>
#include <cstdint>

#define N_NODES 100000
#define N_EDGES 1200000
#define FEATS   64

#define SCAN_TPB   256
#define SCAN_EPT   8
#define SCAN_EPB   (SCAN_TPB * SCAN_EPT)                 // 2048
#define N_SCAN_BLK ((N_NODES + SCAN_EPB - 1) / SCAN_EPB) // 49

// CSR scratch
__device__ int g_cnt[N_NODES];        // degree (histogram)
__device__ int g_start[N_NODES];      // exclusive scan of g_cnt
__device__ int g_fill[N_NODES];       // running fill cursor
__device__ int g_bsum[N_SCAN_BLK];    // per-block scan sums
__device__ int g_srcidx[N_EDGES];     // src node id, grouped by dst

// ---------------------------------------------------------------------------
// K0: zero degree counters
// ---------------------------------------------------------------------------
__global__ void k_zero() {
    int i = blockIdx.x * blockDim.x + threadIdx.x;
    int stride = gridDim.x * blockDim.x;
    for (; i < N_NODES; i += stride) g_cnt[i] = 0;
}

// ---------------------------------------------------------------------------
// K1: histogram of edge_dst  (int atomics, low contention: avg 12/ctr)
// ---------------------------------------------------------------------------
__global__ void k_hist(const int* __restrict__ edst) {
    int i = blockIdx.x * blockDim.x + threadIdx.x;
    if (i < N_EDGES) atomicAdd(&g_cnt[__ldg(&edst[i])], 1);
}

// ---------------------------------------------------------------------------
// K2: per-block exclusive scan of g_cnt -> g_start, block totals -> g_bsum
// ---------------------------------------------------------------------------
__global__ __launch_bounds__(SCAN_TPB)
void k_scan_block() {
    __shared__ int s_wsum[SCAN_TPB / 32];
    __shared__ int s_wexcl[SCAN_TPB / 32];

    int tid  = threadIdx.x;
    int lane = tid & 31, wid = tid >> 5;
    int base = blockIdx.x * SCAN_EPB + tid * SCAN_EPT;

    int v[SCAN_EPT];
    int run = 0;
    #pragma unroll
    for (int k = 0; k < SCAN_EPT; k++) {
        int idx = base + k;
        int t = (idx < N_NODES) ? g_cnt[idx] : 0;
        v[k] = run;            // thread-local exclusive prefix
        run += t;
    }
    int tot = run;

    // warp inclusive scan of per-thread totals
    int x = tot;
    #pragma unroll
    for (int off = 1; off < 32; off <<= 1) {
        int y = __shfl_up_sync(0xFFFFFFFFu, x, off);
        if (lane >= off) x += y;
    }
    if (lane == 31) s_wsum[wid] = x;
    __syncthreads();

    if (wid == 0) {
        int w = (lane < SCAN_TPB / 32) ? s_wsum[lane] : 0;
        int wx = w;
        #pragma unroll
        for (int off = 1; off < 32; off <<= 1) {
            int y = __shfl_up_sync(0xFFFFFFFFu, wx, off);
            if (lane >= off) wx += y;
        }
        if (lane < SCAN_TPB / 32) s_wexcl[lane] = wx - w;
        if (lane == SCAN_TPB / 32 - 1 && blockIdx.x < N_SCAN_BLK)
            g_bsum[blockIdx.x] = wx;   // block total
    }
    __syncthreads();

    int toff = s_wexcl[wid] + (x - tot);
    #pragma unroll
    for (int k = 0; k < SCAN_EPT; k++) {
        int idx = base + k;
        if (idx < N_NODES) g_start[idx] = v[k] + toff;
    }
}

// ---------------------------------------------------------------------------
// K3: exclusive scan of the 49 block sums (single block, 64 threads)
// ---------------------------------------------------------------------------
__global__ void k_scan_top() {
    __shared__ int s_w[2];
    int tid = threadIdx.x;
    int lane = tid & 31, wid = tid >> 5;
    int v = (tid < N_SCAN_BLK) ? g_bsum[tid] : 0;
    int x = v;
    #pragma unroll
    for (int off = 1; off < 32; off <<= 1) {
        int y = __shfl_up_sync(0xFFFFFFFFu, x, off);
        if (lane >= off) x += y;
    }
    if (lane == 31) s_w[wid] = x;
    __syncthreads();
    int add = (wid == 1) ? s_w[0] : 0;
    if (tid < N_SCAN_BLK) g_bsum[tid] = x - v + add;   // exclusive
}

// ---------------------------------------------------------------------------
// K4: add block offsets; init fill cursors
// ---------------------------------------------------------------------------
__global__ void k_scan_add() {
    int i = blockIdx.x * blockDim.x + threadIdx.x;
    if (i >= N_NODES) return;
    int s = g_start[i] + g_bsum[i / SCAN_EPB];
    g_start[i] = s;
    g_fill[i]  = s;
}

// ---------------------------------------------------------------------------
// K5: scatter src ids into CSR order
// ---------------------------------------------------------------------------
__global__ void k_scatter(const int* __restrict__ esrc,
                          const int* __restrict__ edst) {
    int i = blockIdx.x * blockDim.x + threadIdx.x;
    if (i >= N_EDGES) return;
    int d = __ldg(&edst[i]);
    int pos = atomicAdd(&g_fill[d], 1);
    g_srcidx[pos] = __ldg(&esrc[i]);
}

// ---------------------------------------------------------------------------
// K6: fused gather-mean + linear + relu.
// 256 threads = 4 nodes x 64 output lanes. Gather accumulates in registers.
// ---------------------------------------------------------------------------
#define NPB 4
__global__ __launch_bounds__(256, 8)
void k_agg(const float* __restrict__ feat,
           const float* __restrict__ W,
           const float* __restrict__ b,
           float* __restrict__ out) {
    __shared__ float Ws[FEATS][FEATS + 1];   // Ws[d][o] = W[o][d]
    __shared__ float hs[NPB][FEATS];

    int tid = threadIdx.x;
    #pragma unroll
    for (int i = tid; i < FEATS * FEATS; i += 256) {
        int o = i >> 6, d = i & 63;
        Ws[d][o] = W[i];
    }

    int nl = tid >> 6;        // node slot 0..3
    int o  = tid & 63;        // feature lane 0..63
    int node = blockIdx.x * NPB + nl;

    float acc = 0.0f;
    int cnt = 0;
    if (node < N_NODES) {
        int s0 = g_start[node];
        cnt = g_cnt[node];
        int end = s0 + cnt;
        int i = s0;
        // unroll x4 for MLP over L2-latency gathers
        for (; i + 4 <= end; i += 4) {
            int a0 = g_srcidx[i];
            int a1 = g_srcidx[i + 1];
            int a2 = g_srcidx[i + 2];
            int a3 = g_srcidx[i + 3];
            float f0 = __ldg(&feat[(size_t)a0 * FEATS + o]);
            float f1 = __ldg(&feat[(size_t)a1 * FEATS + o]);
            float f2 = __ldg(&feat[(size_t)a2 * FEATS + o]);
            float f3 = __ldg(&feat[(size_t)a3 * FEATS + o]);
            acc += (f0 + f1) + (f2 + f3);
        }
        for (; i < end; i++)
            acc += __ldg(&feat[(size_t)g_srcidx[i] * FEATS + o]);
        acc *= 1.0f / fmaxf((float)cnt, 1.0f);
    }
    hs[nl][o] = acc;
    __syncthreads();

    if (node >= N_NODES) return;

    float r = __ldg(&b[o]);
    #pragma unroll
    for (int d = 0; d < FEATS; d++)
        r = fmaf(Ws[d][o], hs[nl][d], r);

    out[(size_t)node * FEATS + o] = fmaxf(r, 0.0f);
}

// ---------------------------------------------------------------------------
extern "C" void kernel_launch(void* const* d_in, const int* in_sizes, int n_in,
                              void* d_out, int out_size) {
    const float* feat = (const float*)d_in[0];
    const int*   esrc = (const int*)  d_in[1];
    const int*   edst = (const int*)  d_in[2];
    const float* W    = (const float*)d_in[3];
    const float* b    = (const float*)d_in[4];
    float* out = (float*)d_out;

    k_zero<<<128, 256>>>();
    k_hist<<<(N_EDGES + 255) / 256, 256>>>(edst);
    k_scan_block<<<N_SCAN_BLK, SCAN_TPB>>>();
    k_scan_top<<<1, 64>>>();
    k_scan_add<<<(N_NODES + 255) / 256, 256>>>();
    k_scatter<<<(N_EDGES + 255) / 256, 256>>>(esrc, edst);
    k_agg<<<(N_NODES + NPB - 1) / NPB, 256>>>(feat, W, b, out);
}

// round 4
// speedup vs baseline: 1.8349x; 1.7023x over previous
#include <cuda_runtime.h>
#include <cuda_bf16.h>
#include <cstdint>

#define N_NODES 100000
#define N_EDGES 1200000
#define FEATS   64

#define SCAN_TPB   256
#define SCAN_EPT   8
#define SCAN_EPB   (SCAN_TPB * SCAN_EPT)                 // 2048
#define N_SCAN_BLK ((N_NODES + SCAN_EPB - 1) / SCAN_EPB) // 49

// CSR + transformed-feature scratch
__device__ int   g_cnt[N_NODES];
__device__ int   g_start[N_NODES];
__device__ int   g_fill[N_NODES];
__device__ int   g_bsum[N_SCAN_BLK];
__device__ int   g_srcidx[N_EDGES];
__device__ float g_xf[(size_t)N_NODES * FEATS];   // feat @ W^T

typedef unsigned long long ull;

// packed f32x2 FMA: d = a*b + d  (Blackwell FFMA2)
__device__ __forceinline__ void fma2(ull& d, ull a, ull b) {
    asm("fma.rn.f32x2 %0, %1, %2, %0;" : "+l"(d) : "l"(a), "l"(b));
}
__device__ __forceinline__ float2 unpack2(ull v) {
    float2 r;
    asm("mov.b64 {%0, %1}, %2;" : "=f"(r.x), "=f"(r.y) : "l"(v));
    return r;
}

// ---------------------------------------------------------------------------
// K0: zero degree counters
// ---------------------------------------------------------------------------
__global__ void k_zero() {
    int i = blockIdx.x * blockDim.x + threadIdx.x;
    int stride = gridDim.x * blockDim.x;
    for (; i < N_NODES; i += stride) g_cnt[i] = 0;
}

// ---------------------------------------------------------------------------
// K1: histogram of edge_dst
// ---------------------------------------------------------------------------
__global__ void k_hist(const int* __restrict__ edst) {
    int i = blockIdx.x * blockDim.x + threadIdx.x;
    if (i < N_EDGES) atomicAdd(&g_cnt[__ldg(&edst[i])], 1);
}

// ---------------------------------------------------------------------------
// K2: per-block exclusive scan of g_cnt -> g_start, block totals -> g_bsum
// ---------------------------------------------------------------------------
__global__ __launch_bounds__(SCAN_TPB)
void k_scan_block() {
    __shared__ int s_wsum[SCAN_TPB / 32];
    __shared__ int s_wexcl[SCAN_TPB / 32];

    int tid  = threadIdx.x;
    int lane = tid & 31, wid = tid >> 5;
    int base = blockIdx.x * SCAN_EPB + tid * SCAN_EPT;

    int v[SCAN_EPT];
    int run = 0;
    #pragma unroll
    for (int k = 0; k < SCAN_EPT; k++) {
        int idx = base + k;
        int t = (idx < N_NODES) ? g_cnt[idx] : 0;
        v[k] = run;
        run += t;
    }
    int tot = run;

    int x = tot;
    #pragma unroll
    for (int off = 1; off < 32; off <<= 1) {
        int y = __shfl_up_sync(0xFFFFFFFFu, x, off);
        if (lane >= off) x += y;
    }
    if (lane == 31) s_wsum[wid] = x;
    __syncthreads();

    if (wid == 0) {
        int w = (lane < SCAN_TPB / 32) ? s_wsum[lane] : 0;
        int wx = w;
        #pragma unroll
        for (int off = 1; off < 32; off <<= 1) {
            int y = __shfl_up_sync(0xFFFFFFFFu, wx, off);
            if (lane >= off) wx += y;
        }
        if (lane < SCAN_TPB / 32) s_wexcl[lane] = wx - w;
        if (lane == SCAN_TPB / 32 - 1)
            g_bsum[blockIdx.x] = wx;
    }
    __syncthreads();

    int toff = s_wexcl[wid] + (x - tot);
    #pragma unroll
    for (int k = 0; k < SCAN_EPT; k++) {
        int idx = base + k;
        if (idx < N_NODES) g_start[idx] = v[k] + toff;
    }
}

// ---------------------------------------------------------------------------
// K3: exclusive scan of block sums (single block)
// ---------------------------------------------------------------------------
__global__ void k_scan_top() {
    __shared__ int s_w[2];
    int tid = threadIdx.x;
    int lane = tid & 31, wid = tid >> 5;
    int v = (tid < N_SCAN_BLK) ? g_bsum[tid] : 0;
    int x = v;
    #pragma unroll
    for (int off = 1; off < 32; off <<= 1) {
        int y = __shfl_up_sync(0xFFFFFFFFu, x, off);
        if (lane >= off) x += y;
    }
    if (lane == 31) s_w[wid] = x;
    __syncthreads();
    int add = (wid == 1) ? s_w[0] : 0;
    if (tid < N_SCAN_BLK) g_bsum[tid] = x - v + add;
}

// ---------------------------------------------------------------------------
// K4: add block offsets; init fill cursors
// ---------------------------------------------------------------------------
__global__ void k_scan_add() {
    int i = blockIdx.x * blockDim.x + threadIdx.x;
    if (i >= N_NODES) return;
    int s = g_start[i] + g_bsum[i / SCAN_EPB];
    g_start[i] = s;
    g_fill[i]  = s;
}

// ---------------------------------------------------------------------------
// K5: scatter src ids into CSR order
// ---------------------------------------------------------------------------
__global__ void k_scatter(const int* __restrict__ esrc,
                          const int* __restrict__ edst) {
    int i = blockIdx.x * blockDim.x + threadIdx.x;
    if (i >= N_EDGES) return;
    int d = __ldg(&edst[i]);
    int pos = atomicAdd(&g_fill[d], 1);
    g_srcidx[pos] = __ldg(&esrc[i]);
}

// ---------------------------------------------------------------------------
// K6: transform  g_xf = feat @ W^T   (f32x2 packed FMA, W in registers)
// 256 threads: o = tid&63 (output col), ns = tid>>6 (node slot, 4 nodes/thread)
// Tile = 16 nodes. 100000/16 = 6250 tiles exactly.
// ---------------------------------------------------------------------------
#define XT_NODES  16
#define XF_BLOCKS 1184
#define XF_TILES  (N_NODES / XT_NODES)   // 6250

__global__ __launch_bounds__(256)
void k_xform(const float* __restrict__ feat,
             const float* __restrict__ W) {
    __shared__ float Ws[FEATS * 66];        // row o at Ws[o*66 + d]
    __shared__ float fs[XT_NODES * 68];     // node n at fs[n*68 + d]

    int tid = threadIdx.x;
    // cooperative coalesced load of W into shared
    #pragma unroll
    for (int i = tid; i < FEATS * FEATS; i += 256) {
        int o = i >> 6, d = i & 63;
        Ws[o * 66 + d] = W[i];
    }
    __syncthreads();

    int o  = tid & 63;
    int ns = tid >> 6;   // 0..3

    // W row for this output column into registers, packed over d-pairs
    ull wreg[32];
    #pragma unroll
    for (int k = 0; k < 32; k++)
        wreg[k] = *reinterpret_cast<const ull*>(&Ws[o * 66 + 2 * k]);

    for (int t = blockIdx.x; t < XF_TILES; t += XF_BLOCKS) {
        int base = t * XT_NODES;
        __syncthreads();   // protect fs reuse
        // stage 16 node rows (1024 floats = 256 float4, 1 per thread)
        {
            int n  = tid >> 4;
            int dd = (tid & 15) * 4;
            float4 v = *reinterpret_cast<const float4*>(
                &feat[(size_t)(base + n) * FEATS + dd]);
            *reinterpret_cast<float4*>(&fs[n * 68 + dd]) = v;
        }
        __syncthreads();

        ull acc0 = 0, acc1 = 0, acc2 = 0, acc3 = 0;
        #pragma unroll
        for (int k = 0; k < 32; k++) {
            int d = 2 * k;
            ull a0 = *reinterpret_cast<const ull*>(&fs[(ns     ) * 68 + d]);
            ull a1 = *reinterpret_cast<const ull*>(&fs[(ns +  4) * 68 + d]);
            ull a2 = *reinterpret_cast<const ull*>(&fs[(ns +  8) * 68 + d]);
            ull a3 = *reinterpret_cast<const ull*>(&fs[(ns + 12) * 68 + d]);
            fma2(acc0, a0, wreg[k]);
            fma2(acc1, a1, wreg[k]);
            fma2(acc2, a2, wreg[k]);
            fma2(acc3, a3, wreg[k]);
        }
        float2 r0 = unpack2(acc0), r1 = unpack2(acc1),
               r2 = unpack2(acc2), r3 = unpack2(acc3);
        g_xf[(size_t)(base + ns     ) * FEATS + o] = r0.x + r0.y;
        g_xf[(size_t)(base + ns +  4) * FEATS + o] = r1.x + r1.y;
        g_xf[(size_t)(base + ns +  8) * FEATS + o] = r2.x + r2.y;
        g_xf[(size_t)(base + ns + 12) * FEATS + o] = r3.x + r3.y;
    }
}

// ---------------------------------------------------------------------------
// K7: gather-mean over transformed features + bias + relu.
// 16 threads per node, float4 lanes. 100000*16/256 = 6250 blocks exactly.
// ---------------------------------------------------------------------------
__global__ __launch_bounds__(256)
void k_gather(const float* __restrict__ b,
              float* __restrict__ out) {
    int gid  = blockIdx.x * 256 + threadIdx.x;
    int node = gid >> 4;
    int l4   = gid & 15;

    int s0  = g_start[node];
    int cnt = g_cnt[node];
    int end = s0 + cnt;

    float4 acc = make_float4(0.f, 0.f, 0.f, 0.f);
    int i = s0;
    for (; i + 4 <= end; i += 4) {
        int a0 = g_srcidx[i];
        int a1 = g_srcidx[i + 1];
        int a2 = g_srcidx[i + 2];
        int a3 = g_srcidx[i + 3];
        float4 f0 = *reinterpret_cast<const float4*>(&g_xf[(size_t)a0 * FEATS + l4 * 4]);
        float4 f1 = *reinterpret_cast<const float4*>(&g_xf[(size_t)a1 * FEATS + l4 * 4]);
        float4 f2 = *reinterpret_cast<const float4*>(&g_xf[(size_t)a2 * FEATS + l4 * 4]);
        float4 f3 = *reinterpret_cast<const float4*>(&g_xf[(size_t)a3 * FEATS + l4 * 4]);
        acc.x += (f0.x + f1.x) + (f2.x + f3.x);
        acc.y += (f0.y + f1.y) + (f2.y + f3.y);
        acc.z += (f0.z + f1.z) + (f2.z + f3.z);
        acc.w += (f0.w + f1.w) + (f2.w + f3.w);
    }
    for (; i < end; i++) {
        int a = g_srcidx[i];
        float4 f = *reinterpret_cast<const float4*>(&g_xf[(size_t)a * FEATS + l4 * 4]);
        acc.x += f.x; acc.y += f.y; acc.z += f.z; acc.w += f.w;
    }

    float r = 1.0f / fmaxf((float)cnt, 1.0f);
    float4 bb = reinterpret_cast<const float4*>(b)[l4];
    float4 o4;
    o4.x = fmaxf(fmaf(acc.x, r, bb.x), 0.f);
    o4.y = fmaxf(fmaf(acc.y, r, bb.y), 0.f);
    o4.z = fmaxf(fmaf(acc.z, r, bb.z), 0.f);
    o4.w = fmaxf(fmaf(acc.w, r, bb.w), 0.f);
    *reinterpret_cast<float4*>(&out[(size_t)node * FEATS + l4 * 4]) = o4;
}

// ---------------------------------------------------------------------------
extern "C" void kernel_launch(void* const* d_in, const int* in_sizes, int n_in,
                              void* d_out, int out_size) {
    const float* feat = (const float*)d_in[0];
    const int*   esrc = (const int*)  d_in[1];
    const int*   edst = (const int*)  d_in[2];
    const float* W    = (const float*)d_in[3];
    const float* b    = (const float*)d_in[4];
    float* out = (float*)d_out;

    k_zero<<<128, 256>>>();
    k_hist<<<(N_EDGES + 255) / 256, 256>>>(edst);
    k_scan_block<<<N_SCAN_BLK, SCAN_TPB>>>();
    k_scan_top<<<1, 64>>>();
    k_scan_add<<<(N_NODES + 255) / 256, 256>>>();
    k_scatter<<<(N_EDGES + 255) / 256, 256>>>(esrc, edst);
    k_xform<<<XF_BLOCKS, 256>>>(feat, W);
    k_gather<<<100000 * 16 / 256, 256>>>(b, out);
}